// round 3
// baseline (speedup 1.0000x reference)
#include <cuda_runtime.h>
#include <cuda_bf16.h>
#include <math.h>

// Problem constants
#define BATCH 2
#define SEQ 2048
#define DMODEL 2048
#define NHEADS 16
#define DHEAD 128
#define ROWS (BATCH*SEQ)          // 4096
#define SOFTCAP 50.0f
#define ATTN_SCALE 0.08838834764831845f  // 1/sqrt(128)

// ---------------- scratch (device globals; no allocation allowed) -----------
__device__ float g_q[ROWS * DMODEL];
__device__ float g_k[ROWS * DMODEL];
__device__ float g_v[ROWS * DMODEL];
__device__ float g_att[ROWS * DMODEL];

// ---------------- GEMM: C[M,N] = A[M,K] * B[N,K]^T  (fp32, NT) --------------
#define GBM 128
#define GBN 128
#define GBK 8
#define GPAD 4

__global__ __launch_bounds__(256)
void gemm_nt(const float* __restrict__ A, const float* __restrict__ B,
             float* __restrict__ C, int M, int N, int K) {
    __shared__ float As[GBK][GBM + GPAD];
    __shared__ float Bs[GBK][GBN + GPAD];

    const int tid = threadIdx.x;
    const int row0 = blockIdx.y * GBM;
    const int col0 = blockIdx.x * GBN;
    const int tx = tid & 15;     // 0..15 -> N direction
    const int ty = tid >> 4;     // 0..15 -> M direction

    const int lrow = tid >> 1;         // 0..127
    const int lk   = (tid & 1) * 4;    // 0 or 4

    const float* Aptr = A + (size_t)(row0 + lrow) * K + lk;
    const float* Bptr = B + (size_t)(col0 + lrow) * K + lk;

    float acc[8][8];
    #pragma unroll
    for (int i = 0; i < 8; i++)
        #pragma unroll
        for (int j = 0; j < 8; j++) acc[i][j] = 0.f;

    for (int k0 = 0; k0 < K; k0 += GBK) {
        float4 av = *(const float4*)(Aptr + k0);
        float4 bv = *(const float4*)(Bptr + k0);
        As[lk + 0][lrow] = av.x; As[lk + 1][lrow] = av.y;
        As[lk + 2][lrow] = av.z; As[lk + 3][lrow] = av.w;
        Bs[lk + 0][lrow] = bv.x; Bs[lk + 1][lrow] = bv.y;
        Bs[lk + 2][lrow] = bv.z; Bs[lk + 3][lrow] = bv.w;
        __syncthreads();

        #pragma unroll
        for (int kk = 0; kk < GBK; kk++) {
            float a[8], b[8];
            *(float4*)(a)     = *(const float4*)&As[kk][ty * 8];
            *(float4*)(a + 4) = *(const float4*)&As[kk][ty * 8 + 4];
            *(float4*)(b)     = *(const float4*)&Bs[kk][tx * 8];
            *(float4*)(b + 4) = *(const float4*)&Bs[kk][tx * 8 + 4];
            #pragma unroll
            for (int i = 0; i < 8; i++)
                #pragma unroll
                for (int j = 0; j < 8; j++)
                    acc[i][j] += a[i] * b[j];
        }
        __syncthreads();
    }

    #pragma unroll
    for (int i = 0; i < 8; i++) {
        int r = row0 + ty * 8 + i;
        float* cp = C + (size_t)r * N + col0 + tx * 8;
        float4 r0 = make_float4(acc[i][0], acc[i][1], acc[i][2], acc[i][3]);
        float4 r1 = make_float4(acc[i][4], acc[i][5], acc[i][6], acc[i][7]);
        *(float4*)(cp)     = r0;
        *(float4*)(cp + 4) = r1;
    }
}

// --------------- fused RMSNorm + RoPE (in-place, warp per head) -------------
// NOTE: the reference applies RoPE on the (B, H, T, D) tensor with
// n = x.shape[1] == N_HEADS, i.e. the rope table is indexed by HEAD index,
// broadcast over time. Reproduce that exactly: angle index = h, not t.
__global__ __launch_bounds__(128)
void norm_rope(float* __restrict__ buf, const float* __restrict__ w,
               const float* __restrict__ cs, const float* __restrict__ sn) {
    const int warp = threadIdx.x >> 5;
    const int lane = threadIdx.x & 31;
    const int flat = blockIdx.x * 4 + warp;    // (row, head) flattened
    const int row = flat >> 4;                 // /NHEADS
    const int h = flat & 15;

    float* p = buf + (size_t)row * DMODEL + h * DHEAD;
    float4 v = *(float4*)(p + lane * 4);

    float ss = v.x * v.x + v.y * v.y + v.z * v.z + v.w * v.w;
    #pragma unroll
    for (int o = 16; o > 0; o >>= 1) ss += __shfl_xor_sync(0xffffffffu, ss, o);
    float r = rsqrtf(ss * (1.0f / DHEAD) + 1e-6f);

    float4 wv = *(const float4*)(w + lane * 4);
    float x0 = v.x * r * wv.x;
    float x1 = v.y * r * wv.y;
    float x2 = v.z * r * wv.z;
    float x3 = v.w * r * wv.w;

    int i0 = lane * 2;   // rope pair index (0..63)
    // HEAD-indexed rope table (matches reference quirk)
    float c0 = cs[h * 64 + i0],     s0 = sn[h * 64 + i0];
    float c1 = cs[h * 64 + i0 + 1], s1 = sn[h * 64 + i0 + 1];

    float4 o;
    o.x = x0 * c0 - x1 * s0;
    o.y = x0 * s0 + x1 * c0;
    o.z = x2 * c1 - x3 * s1;
    o.w = x2 * s1 + x3 * c1;
    *(float4*)(p + lane * 4) = o;
}

// --------------- flash attention with softcap (fp32, 64x64 tiles) -----------
#define FBM 64
#define FBN 64
#define KSTR 132   // padded stride for K/V tiles (floats)
#define PSTR 68    // padded stride for P tile

__global__ __launch_bounds__(256)
void flash_attn(const float* __restrict__ Q, const float* __restrict__ K,
                const float* __restrict__ V, float* __restrict__ O) {
    extern __shared__ float sm[];
    float* Qs = sm;                          // 64*128
    float* Ks = Qs + FBM * DHEAD;            // 64*132
    float* Vs = Ks + FBN * KSTR;             // 64*132
    float* Ps = Vs + FBN * KSTR;             // 64*68

    const int qtile = gridDim.x - 1 - blockIdx.x;   // heavy tiles first
    const int h = blockIdx.y;
    const int b = blockIdx.z;
    const int tid = threadIdx.x;
    const int tx = tid & 15;
    const int ty = tid >> 4;

    const size_t base = ((size_t)b * SEQ) * DMODEL + (size_t)h * DHEAD;
    const int q0 = qtile * FBM;

    // stage Q tile
    for (int i = tid; i < FBM * (DHEAD / 4); i += 256) {
        int r = i >> 5;
        int c4 = (i & 31) * 4;
        *(float4*)&Qs[r * DHEAD + c4] =
            *(const float4*)&Q[base + (size_t)(q0 + r) * DMODEL + c4];
    }

    float m_r[4], l_r[4];
    float o_acc[4][8];
    #pragma unroll
    for (int i = 0; i < 4; i++) {
        m_r[i] = -1e30f; l_r[i] = 0.f;
        #pragma unroll
        for (int j = 0; j < 8; j++) o_acc[i][j] = 0.f;
    }
    __syncthreads();

    const int ntiles = qtile + 1;
    for (int kt = 0; kt < ntiles; kt++) {
        const int k0 = kt * FBN;
        // stage K & V tiles
        for (int i = tid; i < FBN * 32; i += 256) {
            int r = i >> 5;
            int c4 = (i & 31) * 4;
            *(float4*)&Ks[r * KSTR + c4] =
                *(const float4*)&K[base + (size_t)(k0 + r) * DMODEL + c4];
            *(float4*)&Vs[r * KSTR + c4] =
                *(const float4*)&V[base + (size_t)(k0 + r) * DMODEL + c4];
        }
        __syncthreads();

        // S = Q K^T ; thread owns rows ty*4+i, cols tx+16*j
        float s[4][4];
        #pragma unroll
        for (int i = 0; i < 4; i++)
            #pragma unroll
            for (int j = 0; j < 4; j++) s[i][j] = 0.f;

        #pragma unroll 4
        for (int d = 0; d < DHEAD; d += 4) {
            float4 qv[4], kv[4];
            #pragma unroll
            for (int i = 0; i < 4; i++)
                qv[i] = *(const float4*)&Qs[(ty * 4 + i) * DHEAD + d];
            #pragma unroll
            for (int j = 0; j < 4; j++)
                kv[j] = *(const float4*)&Ks[(tx + 16 * j) * KSTR + d];
            #pragma unroll
            for (int i = 0; i < 4; i++)
                #pragma unroll
                for (int j = 0; j < 4; j++)
                    s[i][j] += qv[i].x * kv[j].x + qv[i].y * kv[j].y +
                               qv[i].z * kv[j].z + qv[i].w * kv[j].w;
        }

        // softcap + causal mask + online softmax
        float alpha[4];
        #pragma unroll
        for (int i = 0; i < 4; i++) {
            const int qg = q0 + ty * 4 + i;
            float sc[4];
            float mx = -1e30f;
            #pragma unroll
            for (int j = 0; j < 4; j++) {
                int kg = k0 + tx + 16 * j;
                float v = SOFTCAP * tanhf(s[i][j] * (ATTN_SCALE / SOFTCAP));
                v = (kg <= qg) ? v : -1e30f;
                sc[j] = v;
                mx = fmaxf(mx, v);
            }
            #pragma unroll
            for (int o = 1; o < 16; o <<= 1)
                mx = fmaxf(mx, __shfl_xor_sync(0xffffffffu, mx, o));
            float mnew = fmaxf(m_r[i], mx);
            float al = __expf(m_r[i] - mnew);
            m_r[i] = mnew;
            float ls = 0.f;
            float p[4];
            #pragma unroll
            for (int j = 0; j < 4; j++) {
                p[j] = __expf(sc[j] - mnew);
                ls += p[j];
            }
            #pragma unroll
            for (int o = 1; o < 16; o <<= 1)
                ls += __shfl_xor_sync(0xffffffffu, ls, o);
            l_r[i] = l_r[i] * al + ls;
            alpha[i] = al;
            #pragma unroll
            for (int j = 0; j < 4; j++)
                Ps[(ty * 4 + i) * PSTR + tx + 16 * j] = p[j];
        }
        __syncthreads();

        // O = O*alpha + P V ; thread owns rows ty*4+i, dims tx*8..tx*8+7
        #pragma unroll
        for (int i = 0; i < 4; i++)
            #pragma unroll
            for (int j = 0; j < 8; j++) o_acc[i][j] *= alpha[i];

        #pragma unroll 4
        for (int c = 0; c < FBN; c++) {
            float pv[4];
            #pragma unroll
            for (int i = 0; i < 4; i++) pv[i] = Ps[(ty * 4 + i) * PSTR + c];
            float4 v0 = *(const float4*)&Vs[c * KSTR + tx * 8];
            float4 v1 = *(const float4*)&Vs[c * KSTR + tx * 8 + 4];
            #pragma unroll
            for (int i = 0; i < 4; i++) {
                o_acc[i][0] += pv[i] * v0.x;
                o_acc[i][1] += pv[i] * v0.y;
                o_acc[i][2] += pv[i] * v0.z;
                o_acc[i][3] += pv[i] * v0.w;
                o_acc[i][4] += pv[i] * v1.x;
                o_acc[i][5] += pv[i] * v1.y;
                o_acc[i][6] += pv[i] * v1.z;
                o_acc[i][7] += pv[i] * v1.w;
            }
        }
        __syncthreads();
    }

    // epilogue: normalize and store
    #pragma unroll
    for (int i = 0; i < 4; i++) {
        float inv = 1.0f / l_r[i];
        int qg = q0 + ty * 4 + i;
        float4 r0 = make_float4(o_acc[i][0] * inv, o_acc[i][1] * inv,
                                o_acc[i][2] * inv, o_acc[i][3] * inv);
        float4 r1 = make_float4(o_acc[i][4] * inv, o_acc[i][5] * inv,
                                o_acc[i][6] * inv, o_acc[i][7] * inv);
        float* op = O + base + (size_t)qg * DMODEL + tx * 8;
        *(float4*)(op)     = r0;
        *(float4*)(op + 4) = r1;
    }
}

#define FLASH_SMEM ((FBM * DHEAD + 2 * FBN * KSTR + FBM * PSTR) * 4)

// ----------------------------- launch -------------------------------------
extern "C" void kernel_launch(void* const* d_in, const int* in_sizes, int n_in,
                              void* d_out, int out_size) {
    const float* x        = (const float*)d_in[0];
    const float* wq       = (const float*)d_in[1];
    const float* wk       = (const float*)d_in[2];
    const float* wv       = (const float*)d_in[3];
    const float* wo       = (const float*)d_in[4];
    const float* q_norm_w = (const float*)d_in[5];
    const float* k_norm_w = (const float*)d_in[6];
    const float* rope_cos = (const float*)d_in[7];
    const float* rope_sin = (const float*)d_in[8];
    float* out = (float*)d_out;

    float *qb, *kb, *vb, *ab;
    cudaGetSymbolAddress((void**)&qb, g_q);
    cudaGetSymbolAddress((void**)&kb, g_k);
    cudaGetSymbolAddress((void**)&vb, g_v);
    cudaGetSymbolAddress((void**)&ab, g_att);

    cudaFuncSetAttribute(flash_attn, cudaFuncAttributeMaxDynamicSharedMemorySize,
                         FLASH_SMEM);

    dim3 ggrid(DMODEL / GBN, ROWS / GBM);   // 16 x 32
    gemm_nt<<<ggrid, 256>>>(x, wq, qb, ROWS, DMODEL, DMODEL);
    gemm_nt<<<ggrid, 256>>>(x, wk, kb, ROWS, DMODEL, DMODEL);
    gemm_nt<<<ggrid, 256>>>(x, wv, vb, ROWS, DMODEL, DMODEL);

    int nr_blocks = ROWS * NHEADS / 4;      // 16384
    norm_rope<<<nr_blocks, 128>>>(qb, q_norm_w, rope_cos, rope_sin);
    norm_rope<<<nr_blocks, 128>>>(kb, k_norm_w, rope_cos, rope_sin);

    dim3 fgrid(SEQ / FBM, NHEADS, BATCH);   // 32 x 16 x 2
    flash_attn<<<fgrid, 256, FLASH_SMEM>>>(qb, kb, vb, ab);

    gemm_nt<<<ggrid, 256>>>(ab, wo, out, ROWS, DMODEL, DMODEL);
}

// round 7
// speedup vs baseline: 1.7857x; 1.7857x over previous
#include <cuda_runtime.h>
#include <cuda_bf16.h>
#include <math.h>
#include <stdint.h>

// Problem constants
#define BATCH 2
#define SEQ 2048
#define DMODEL 2048
#define NHEADS 16
#define DHEAD 128
#define ROWS (BATCH*SEQ)          // 4096
#define SOFTCAP 50.0f
#define ATTN_SCALE 0.08838834764831845f  // 1/sqrt(128)

// ---------------- scratch (device globals; no allocation allowed) -----------
__device__ float g_q[ROWS * DMODEL];
__device__ float g_k[ROWS * DMODEL];
__device__ float g_v[ROWS * DMODEL];
__device__ float g_att[ROWS * DMODEL];

__device__ __nv_bfloat16 g_xh[ROWS * DMODEL];
__device__ __nv_bfloat16 g_xl[ROWS * DMODEL];
__device__ __nv_bfloat16 g_ah[ROWS * DMODEL];
__device__ __nv_bfloat16 g_al[ROWS * DMODEL];
__device__ __nv_bfloat16 g_wqh[DMODEL * DMODEL];
__device__ __nv_bfloat16 g_wql[DMODEL * DMODEL];
__device__ __nv_bfloat16 g_wkh[DMODEL * DMODEL];
__device__ __nv_bfloat16 g_wkl[DMODEL * DMODEL];
__device__ __nv_bfloat16 g_wvh[DMODEL * DMODEL];
__device__ __nv_bfloat16 g_wvl[DMODEL * DMODEL];
__device__ __nv_bfloat16 g_woh[DMODEL * DMODEL];
__device__ __nv_bfloat16 g_wol[DMODEL * DMODEL];

// ======================= PTX helpers (baseline PTX only!) ===================
// NOTE: harness compiles PTX at compute_103 (no 'a'): tcgen05/TMEM are NOT
// available. mma.sync / ldmatrix / cp.async are baseline-PTX and map to
// HMMA / LDSM / LDGSTS on sm_103a.
__device__ __forceinline__ uint32_t smem_u32(const void* p) {
    uint32_t a;
    asm("{ .reg .u64 t; cvta.to.shared.u64 t, %1; cvt.u32.u64 %0, t; }"
        : "=r"(a) : "l"(p));
    return a;
}
#define CP_ASYNC16(dst, src) \
    asm volatile("cp.async.cg.shared.global [%0], [%1], 16;" :: "r"(dst), "l"(src))
#define CP_COMMIT() asm volatile("cp.async.commit_group;" ::: "memory")
#define CP_WAIT(n)  asm volatile("cp.async.wait_group %0;" :: "n"(n) : "memory")

#define LDSM_X4(r0, r1, r2, r3, addr) \
    asm volatile("ldmatrix.sync.aligned.m8n8.x4.shared.b16 {%0,%1,%2,%3}, [%4];" \
        : "=r"(r0), "=r"(r1), "=r"(r2), "=r"(r3) : "r"(addr))

__device__ __forceinline__ void mma16816(float* c, const uint32_t* a,
                                         uint32_t b0, uint32_t b1) {
    asm volatile("mma.sync.aligned.m16n8k16.row.col.f32.bf16.bf16.f32 "
        "{%0,%1,%2,%3}, {%4,%5,%6,%7}, {%8,%9}, {%0,%1,%2,%3};"
        : "+f"(c[0]), "+f"(c[1]), "+f"(c[2]), "+f"(c[3])
        : "r"(a[0]), "r"(a[1]), "r"(a[2]), "r"(a[3]), "r"(b0), "r"(b1));
}

// =================== split fp32 -> (bf16 hi, bf16 lo) =======================
__global__ __launch_bounds__(256)
void split_bf16(const float* __restrict__ in, __nv_bfloat16* __restrict__ hi,
                __nv_bfloat16* __restrict__ lo, int n4) {
    int i = blockIdx.x * blockDim.x + threadIdx.x;
    if (i >= n4) return;
    float4 v = ((const float4*)in)[i];
    __nv_bfloat16 h0 = __float2bfloat16_rn(v.x);
    __nv_bfloat16 h1 = __float2bfloat16_rn(v.y);
    __nv_bfloat16 h2 = __float2bfloat16_rn(v.z);
    __nv_bfloat16 h3 = __float2bfloat16_rn(v.w);
    __nv_bfloat16 l0 = __float2bfloat16_rn(v.x - __bfloat162float(h0));
    __nv_bfloat16 l1 = __float2bfloat16_rn(v.y - __bfloat162float(h1));
    __nv_bfloat16 l2 = __float2bfloat16_rn(v.z - __bfloat162float(h2));
    __nv_bfloat16 l3 = __float2bfloat16_rn(v.w - __bfloat162float(h3));
    __nv_bfloat162* hp = (__nv_bfloat162*)hi;
    __nv_bfloat162* lp = (__nv_bfloat162*)lo;
    hp[2*i]   = __nv_bfloat162(h0, h1);
    hp[2*i+1] = __nv_bfloat162(h2, h3);
    lp[2*i]   = __nv_bfloat162(l0, l1);
    lp[2*i+1] = __nv_bfloat162(l2, l3);
}

// ============== mma.sync bf16 GEMM: C[M,N] = A[M,K] @ B[N,K]^T ==============
// 3xBF16 split: C = Ah*Bh + Ah*Bl + Al*Bh (error ~ eps^2 ~ 1e-5).
#define BM 128
#define BN 128
#define BK 32                    // bf16 K elements per stage
#define NKC (DMODEL / BK)        // 64
#define LDT 40                   // padded smem row stride (elements) = 80 B
#define TILE_B (BM * LDT * 2)    // 10240 bytes per sub-tile
#define STAGE_B (4 * TILE_B)     // Ah, Al, Bh, Bl = 40960
#define GEMM_SMEM (2 * STAGE_B)  // 81920

__device__ __forceinline__ void load_stage(uint32_t sb, int buf,
                                           const __nv_bfloat16* __restrict__ Ah,
                                           const __nv_bfloat16* __restrict__ Al,
                                           const __nv_bfloat16* __restrict__ Bh,
                                           const __nv_bfloat16* __restrict__ Bl,
                                           int m0, int n0, int kc, int tid) {
    const uint32_t st = sb + buf * STAGE_B;
    const __nv_bfloat16* srcs[4] = {
        Ah + (size_t)m0 * DMODEL + kc * BK,
        Al + (size_t)m0 * DMODEL + kc * BK,
        Bh + (size_t)n0 * DMODEL + kc * BK,
        Bl + (size_t)n0 * DMODEL + kc * BK };
    #pragma unroll
    for (int t = 0; t < 4; t++) {
        #pragma unroll
        for (int it = 0; it < 2; it++) {
            int idx = tid + it * 256;        // 0..511
            int r = idx >> 2;                // row 0..127
            int ch = idx & 3;                // 16B chunk
            const __nv_bfloat16* g = srcs[t] + (size_t)r * DMODEL + ch * 8;
            uint32_t d = st + t * TILE_B + r * (LDT * 2) + ch * 16;
            CP_ASYNC16(d, g);
        }
    }
}

__global__ __launch_bounds__(256)
void gemm_mma(const __nv_bfloat16* __restrict__ Ah, const __nv_bfloat16* __restrict__ Al,
              const __nv_bfloat16* __restrict__ Bh, const __nv_bfloat16* __restrict__ Bl,
              float* __restrict__ C, int M, int N) {
    extern __shared__ char smem[];
    const uint32_t sb = smem_u32(smem);
    const int tid = threadIdx.x;
    const int wid = tid >> 5;
    const int lane = tid & 31;
    const int wm = wid & 3;          // warp M index (4)
    const int wn = wid >> 2;         // warp N index (2)
    const int m0 = blockIdx.y * BM;
    const int n0 = blockIdx.x * BN;

    float acc[2][8][4];
    #pragma unroll
    for (int i = 0; i < 2; i++)
        #pragma unroll
        for (int j = 0; j < 8; j++)
            #pragma unroll
            for (int k = 0; k < 4; k++) acc[i][j][k] = 0.f;

    load_stage(sb, 0, Ah, Al, Bh, Bl, m0, n0, 0, tid);
    CP_COMMIT();

    // per-thread ldmatrix base offsets
    const int lrow = lane & 15;
    const int lcol = (lane >> 4) * 16;   // byte offset for k-half

    for (int kc = 0; kc < NKC; kc++) {
        if (kc + 1 < NKC) {
            load_stage(sb, (kc + 1) & 1, Ah, Al, Bh, Bl, m0, n0, kc + 1, tid);
            CP_COMMIT();
            CP_WAIT(1);
        } else {
            CP_WAIT(0);
        }
        __syncthreads();

        const uint32_t st = sb + (kc & 1) * STAGE_B;
        const uint32_t aoff = st;                    // Ah
        const uint32_t boff = st + 2 * TILE_B;       // Bh

        #pragma unroll
        for (int ks = 0; ks < 2; ks++) {
            uint32_t ah[2][4], al[2][4], bh[4][4], bl[4][4];
            #pragma unroll
            for (int mi = 0; mi < 2; mi++) {
                uint32_t ra = aoff + (uint32_t)(wm * 32 + mi * 16 + lrow) * (LDT * 2)
                            + ks * 32 + lcol;
                LDSM_X4(ah[mi][0], ah[mi][1], ah[mi][2], ah[mi][3], ra);
                LDSM_X4(al[mi][0], al[mi][1], al[mi][2], al[mi][3], ra + TILE_B);
            }
            #pragma unroll
            for (int ni = 0; ni < 4; ni++) {
                uint32_t rb = boff + (uint32_t)(wn * 64 + ni * 16 + lrow) * (LDT * 2)
                            + ks * 32 + lcol;
                LDSM_X4(bh[ni][0], bh[ni][1], bh[ni][2], bh[ni][3], rb);
                LDSM_X4(bl[ni][0], bl[ni][1], bl[ni][2], bl[ni][3], rb + TILE_B);
            }
            #pragma unroll
            for (int mi = 0; mi < 2; mi++) {
                #pragma unroll
                for (int nj = 0; nj < 8; nj++) {
                    const int ni = nj >> 1, hh = nj & 1;
                    mma16816(acc[mi][nj], ah[mi], bh[ni][hh], bh[ni][hh + 2]);
                    mma16816(acc[mi][nj], ah[mi], bl[ni][hh], bl[ni][hh + 2]);
                    mma16816(acc[mi][nj], al[mi], bh[ni][hh], bh[ni][hh + 2]);
                }
            }
        }
        __syncthreads();
    }

    // epilogue: direct fp32 stores
    const int mbase = m0 + wm * 32;
    const int nbase = n0 + wn * 64;
    #pragma unroll
    for (int mi = 0; mi < 2; mi++) {
        #pragma unroll
        for (int nj = 0; nj < 8; nj++) {
            int r = mbase + mi * 16 + (lane >> 2);
            int c = nbase + nj * 8 + (lane & 3) * 2;
            *(float2*)&C[(size_t)r * N + c] =
                make_float2(acc[mi][nj][0], acc[mi][nj][1]);
            *(float2*)&C[(size_t)(r + 8) * N + c] =
                make_float2(acc[mi][nj][2], acc[mi][nj][3]);
        }
    }
}

// --------------- fused RMSNorm + RoPE (in-place, warp per head) -------------
// Reference quirk: RoPE applied on (B,H,T,D) with n = shape[1] == N_HEADS ->
// rope table indexed by HEAD index, broadcast over time.
__global__ __launch_bounds__(128)
void norm_rope(float* __restrict__ buf, const float* __restrict__ w,
               const float* __restrict__ cs, const float* __restrict__ sn) {
    const int warp = threadIdx.x >> 5;
    const int lane = threadIdx.x & 31;
    const int flat = blockIdx.x * 4 + warp;
    const int row = flat >> 4;
    const int h = flat & 15;

    float* p = buf + (size_t)row * DMODEL + h * DHEAD;
    float4 v = *(float4*)(p + lane * 4);

    float ss = v.x * v.x + v.y * v.y + v.z * v.z + v.w * v.w;
    #pragma unroll
    for (int o = 16; o > 0; o >>= 1) ss += __shfl_xor_sync(0xffffffffu, ss, o);
    float r = rsqrtf(ss * (1.0f / DHEAD) + 1e-6f);

    float4 wv = *(const float4*)(w + lane * 4);
    float x0 = v.x * r * wv.x;
    float x1 = v.y * r * wv.y;
    float x2 = v.z * r * wv.z;
    float x3 = v.w * r * wv.w;

    int i0 = lane * 2;
    float c0 = cs[h * 64 + i0],     s0 = sn[h * 64 + i0];
    float c1 = cs[h * 64 + i0 + 1], s1 = sn[h * 64 + i0 + 1];

    float4 o;
    o.x = x0 * c0 - x1 * s0;
    o.y = x0 * s0 + x1 * c0;
    o.z = x2 * c1 - x3 * s1;
    o.w = x2 * s1 + x3 * c1;
    *(float4*)(p + lane * 4) = o;
}

// --------------- flash attention with softcap (fp32, 64x64 tiles) -----------
#define FBM 64
#define FBN 64
#define KSTR 132
#define PSTR 68

__global__ __launch_bounds__(256)
void flash_attn(const float* __restrict__ Q, const float* __restrict__ K,
                const float* __restrict__ V, float* __restrict__ O) {
    extern __shared__ float sm[];
    float* Qs = sm;
    float* Ks = Qs + FBM * DHEAD;
    float* Vs = Ks + FBN * KSTR;
    float* Ps = Vs + FBN * KSTR;

    const int qtile = gridDim.x - 1 - blockIdx.x;
    const int h = blockIdx.y;
    const int b = blockIdx.z;
    const int tid = threadIdx.x;
    const int tx = tid & 15;
    const int ty = tid >> 4;

    const size_t base = ((size_t)b * SEQ) * DMODEL + (size_t)h * DHEAD;
    const int q0 = qtile * FBM;

    for (int i = tid; i < FBM * (DHEAD / 4); i += 256) {
        int r = i >> 5;
        int c4 = (i & 31) * 4;
        *(float4*)&Qs[r * DHEAD + c4] =
            *(const float4*)&Q[base + (size_t)(q0 + r) * DMODEL + c4];
    }

    float m_r[4], l_r[4];
    float o_acc[4][8];
    #pragma unroll
    for (int i = 0; i < 4; i++) {
        m_r[i] = -1e30f; l_r[i] = 0.f;
        #pragma unroll
        for (int j = 0; j < 8; j++) o_acc[i][j] = 0.f;
    }
    __syncthreads();

    const int ntiles = qtile + 1;
    for (int kt = 0; kt < ntiles; kt++) {
        const int k0 = kt * FBN;
        for (int i = tid; i < FBN * 32; i += 256) {
            int r = i >> 5;
            int c4 = (i & 31) * 4;
            *(float4*)&Ks[r * KSTR + c4] =
                *(const float4*)&K[base + (size_t)(k0 + r) * DMODEL + c4];
            *(float4*)&Vs[r * KSTR + c4] =
                *(const float4*)&V[base + (size_t)(k0 + r) * DMODEL + c4];
        }
        __syncthreads();

        float s[4][4];
        #pragma unroll
        for (int i = 0; i < 4; i++)
            #pragma unroll
            for (int j = 0; j < 4; j++) s[i][j] = 0.f;

        #pragma unroll 4
        for (int d = 0; d < DHEAD; d += 4) {
            float4 qv[4], kv[4];
            #pragma unroll
            for (int i = 0; i < 4; i++)
                qv[i] = *(const float4*)&Qs[(ty * 4 + i) * DHEAD + d];
            #pragma unroll
            for (int j = 0; j < 4; j++)
                kv[j] = *(const float4*)&Ks[(tx + 16 * j) * KSTR + d];
            #pragma unroll
            for (int i = 0; i < 4; i++)
                #pragma unroll
                for (int j = 0; j < 4; j++)
                    s[i][j] += qv[i].x * kv[j].x + qv[i].y * kv[j].y +
                               qv[i].z * kv[j].z + qv[i].w * kv[j].w;
        }

        float alpha[4];
        #pragma unroll
        for (int i = 0; i < 4; i++) {
            const int qg = q0 + ty * 4 + i;
            float sc[4];
            float mx = -1e30f;
            #pragma unroll
            for (int j = 0; j < 4; j++) {
                int kg = k0 + tx + 16 * j;
                float v = SOFTCAP * tanhf(s[i][j] * (ATTN_SCALE / SOFTCAP));
                v = (kg <= qg) ? v : -1e30f;
                sc[j] = v;
                mx = fmaxf(mx, v);
            }
            #pragma unroll
            for (int o = 1; o < 16; o <<= 1)
                mx = fmaxf(mx, __shfl_xor_sync(0xffffffffu, mx, o));
            float mnew = fmaxf(m_r[i], mx);
            float al = __expf(m_r[i] - mnew);
            m_r[i] = mnew;
            float ls = 0.f;
            float p[4];
            #pragma unroll
            for (int j = 0; j < 4; j++) {
                p[j] = __expf(sc[j] - mnew);
                ls += p[j];
            }
            #pragma unroll
            for (int o = 1; o < 16; o <<= 1)
                ls += __shfl_xor_sync(0xffffffffu, ls, o);
            l_r[i] = l_r[i] * al + ls;
            alpha[i] = al;
            #pragma unroll
            for (int j = 0; j < 4; j++)
                Ps[(ty * 4 + i) * PSTR + tx + 16 * j] = p[j];
        }
        __syncthreads();

        #pragma unroll
        for (int i = 0; i < 4; i++)
            #pragma unroll
            for (int j = 0; j < 8; j++) o_acc[i][j] *= alpha[i];

        #pragma unroll 4
        for (int c = 0; c < FBN; c++) {
            float pv[4];
            #pragma unroll
            for (int i = 0; i < 4; i++) pv[i] = Ps[(ty * 4 + i) * PSTR + c];
            float4 v0 = *(const float4*)&Vs[c * KSTR + tx * 8];
            float4 v1 = *(const float4*)&Vs[c * KSTR + tx * 8 + 4];
            #pragma unroll
            for (int i = 0; i < 4; i++) {
                o_acc[i][0] += pv[i] * v0.x;
                o_acc[i][1] += pv[i] * v0.y;
                o_acc[i][2] += pv[i] * v0.z;
                o_acc[i][3] += pv[i] * v0.w;
                o_acc[i][4] += pv[i] * v1.x;
                o_acc[i][5] += pv[i] * v1.y;
                o_acc[i][6] += pv[i] * v1.z;
                o_acc[i][7] += pv[i] * v1.w;
            }
        }
        __syncthreads();
    }

    #pragma unroll
    for (int i = 0; i < 4; i++) {
        float inv = 1.0f / l_r[i];
        int qg = q0 + ty * 4 + i;
        float4 r0 = make_float4(o_acc[i][0] * inv, o_acc[i][1] * inv,
                                o_acc[i][2] * inv, o_acc[i][3] * inv);
        float4 r1 = make_float4(o_acc[i][4] * inv, o_acc[i][5] * inv,
                                o_acc[i][6] * inv, o_acc[i][7] * inv);
        float* op = O + base + (size_t)qg * DMODEL + tx * 8;
        *(float4*)(op)     = r0;
        *(float4*)(op + 4) = r1;
    }
}

#define FLASH_SMEM ((FBM * DHEAD + 2 * FBN * KSTR + FBM * PSTR) * 4)

// ----------------------------- launch -------------------------------------
extern "C" void kernel_launch(void* const* d_in, const int* in_sizes, int n_in,
                              void* d_out, int out_size) {
    const float* x        = (const float*)d_in[0];
    const float* wq       = (const float*)d_in[1];
    const float* wk       = (const float*)d_in[2];
    const float* wv       = (const float*)d_in[3];
    const float* wo       = (const float*)d_in[4];
    const float* q_norm_w = (const float*)d_in[5];
    const float* k_norm_w = (const float*)d_in[6];
    const float* rope_cos = (const float*)d_in[7];
    const float* rope_sin = (const float*)d_in[8];
    float* out = (float*)d_out;

    float *qb, *kb, *vb, *ab;
    cudaGetSymbolAddress((void**)&qb, g_q);
    cudaGetSymbolAddress((void**)&kb, g_k);
    cudaGetSymbolAddress((void**)&vb, g_v);
    cudaGetSymbolAddress((void**)&ab, g_att);
    __nv_bfloat16 *xh, *xl, *ah, *al;
    __nv_bfloat16 *wqh, *wql, *wkh, *wkl, *wvh, *wvl, *woh, *wol;
    cudaGetSymbolAddress((void**)&xh, g_xh);   cudaGetSymbolAddress((void**)&xl, g_xl);
    cudaGetSymbolAddress((void**)&ah, g_ah);   cudaGetSymbolAddress((void**)&al, g_al);
    cudaGetSymbolAddress((void**)&wqh, g_wqh); cudaGetSymbolAddress((void**)&wql, g_wql);
    cudaGetSymbolAddress((void**)&wkh, g_wkh); cudaGetSymbolAddress((void**)&wkl, g_wkl);
    cudaGetSymbolAddress((void**)&wvh, g_wvh); cudaGetSymbolAddress((void**)&wvl, g_wvl);
    cudaGetSymbolAddress((void**)&woh, g_woh); cudaGetSymbolAddress((void**)&wol, g_wol);

    cudaFuncSetAttribute(flash_attn, cudaFuncAttributeMaxDynamicSharedMemorySize,
                         FLASH_SMEM);
    cudaFuncSetAttribute(gemm_mma, cudaFuncAttributeMaxDynamicSharedMemorySize,
                         GEMM_SMEM);

    // split conversions
    const int NX4 = ROWS * DMODEL / 4;
    const int NW4 = DMODEL * DMODEL / 4;
    split_bf16<<<NX4 / 256, 256>>>(x,  xh,  xl,  NX4);
    split_bf16<<<NW4 / 256, 256>>>(wq, wqh, wql, NW4);
    split_bf16<<<NW4 / 256, 256>>>(wk, wkh, wkl, NW4);
    split_bf16<<<NW4 / 256, 256>>>(wv, wvh, wvl, NW4);
    split_bf16<<<NW4 / 256, 256>>>(wo, woh, wol, NW4);

    // QKV projections on tensor cores (mma.sync HMMA path)
    dim3 tgrid(DMODEL / BN, ROWS / BM);   // 16 x 32
    gemm_mma<<<tgrid, 256, GEMM_SMEM>>>(xh, xl, wqh, wql, qb, ROWS, DMODEL);
    gemm_mma<<<tgrid, 256, GEMM_SMEM>>>(xh, xl, wkh, wkl, kb, ROWS, DMODEL);
    gemm_mma<<<tgrid, 256, GEMM_SMEM>>>(xh, xl, wvh, wvl, vb, ROWS, DMODEL);

    int nr_blocks = ROWS * NHEADS / 4;
    norm_rope<<<nr_blocks, 128>>>(qb, q_norm_w, rope_cos, rope_sin);
    norm_rope<<<nr_blocks, 128>>>(kb, k_norm_w, rope_cos, rope_sin);

    dim3 fgrid(SEQ / FBM, NHEADS, BATCH);
    flash_attn<<<fgrid, 256, FLASH_SMEM>>>(qb, kb, vb, ab);

    // output projection
    split_bf16<<<NX4 / 256, 256>>>(ab, ah, al, NX4);
    gemm_mma<<<tgrid, 256, GEMM_SMEM>>>(ah, al, woh, wol, out, ROWS, DMODEL);
}

// round 8
// speedup vs baseline: 2.6759x; 1.4985x over previous
#include <cuda_runtime.h>
#include <cuda_bf16.h>
#include <math.h>
#include <stdint.h>

// Problem constants
#define BATCH 2
#define SEQ 2048
#define DMODEL 2048
#define NHEADS 16
#define DHEAD 128
#define ROWS (BATCH*SEQ)          // 4096
#define SOFTCAP 50.0f
#define ATTN_SCALE 0.08838834764831845f  // 1/sqrt(128)

// ---------------- scratch (device globals; no allocation allowed) -----------
__device__ float g_q[ROWS * DMODEL];
__device__ float g_k[ROWS * DMODEL];
__device__ float g_v[ROWS * DMODEL];
__device__ float g_att[ROWS * DMODEL];

__device__ __nv_bfloat16 g_xh[ROWS * DMODEL];
__device__ __nv_bfloat16 g_xl[ROWS * DMODEL];
__device__ __nv_bfloat16 g_ah[ROWS * DMODEL];
__device__ __nv_bfloat16 g_al[ROWS * DMODEL];
__device__ __nv_bfloat16 g_qh[ROWS * DMODEL];
__device__ __nv_bfloat16 g_ql[ROWS * DMODEL];
__device__ __nv_bfloat16 g_kh[ROWS * DMODEL];
__device__ __nv_bfloat16 g_kl[ROWS * DMODEL];
__device__ __nv_bfloat16 g_vh[ROWS * DMODEL];
__device__ __nv_bfloat16 g_vl[ROWS * DMODEL];
__device__ __nv_bfloat16 g_wqh[DMODEL * DMODEL];
__device__ __nv_bfloat16 g_wql[DMODEL * DMODEL];
__device__ __nv_bfloat16 g_wkh[DMODEL * DMODEL];
__device__ __nv_bfloat16 g_wkl[DMODEL * DMODEL];
__device__ __nv_bfloat16 g_wvh[DMODEL * DMODEL];
__device__ __nv_bfloat16 g_wvl[DMODEL * DMODEL];
__device__ __nv_bfloat16 g_woh[DMODEL * DMODEL];
__device__ __nv_bfloat16 g_wol[DMODEL * DMODEL];

// ======================= PTX helpers (baseline PTX only!) ===================
// Harness compiles at compute_103 (no 'a'): tcgen05/TMEM unavailable.
// mma.sync / ldmatrix / cp.async are baseline and map to HMMA/LDSM/LDGSTS.
__device__ __forceinline__ uint32_t smem_u32(const void* p) {
    uint32_t a;
    asm("{ .reg .u64 t; cvta.to.shared.u64 t, %1; cvt.u32.u64 %0, t; }"
        : "=r"(a) : "l"(p));
    return a;
}
#define CP_ASYNC16(dst, src) \
    asm volatile("cp.async.cg.shared.global [%0], [%1], 16;" :: "r"(dst), "l"(src))
#define CP_COMMIT() asm volatile("cp.async.commit_group;" ::: "memory")
#define CP_WAIT(n)  asm volatile("cp.async.wait_group %0;" :: "n"(n) : "memory")

#define LDSM_X4(r0, r1, r2, r3, addr) \
    asm volatile("ldmatrix.sync.aligned.m8n8.x4.shared.b16 {%0,%1,%2,%3}, [%4];" \
        : "=r"(r0), "=r"(r1), "=r"(r2), "=r"(r3) : "r"(addr))
#define LDSM_X4_T(r0, r1, r2, r3, addr) \
    asm volatile("ldmatrix.sync.aligned.m8n8.x4.trans.shared.b16 {%0,%1,%2,%3}, [%4];" \
        : "=r"(r0), "=r"(r1), "=r"(r2), "=r"(r3) : "r"(addr))

__device__ __forceinline__ void mma16816(float* c, const uint32_t* a,
                                         uint32_t b0, uint32_t b1) {
    asm volatile("mma.sync.aligned.m16n8k16.row.col.f32.bf16.bf16.f32 "
        "{%0,%1,%2,%3}, {%4,%5,%6,%7}, {%8,%9}, {%0,%1,%2,%3};"
        : "+f"(c[0]), "+f"(c[1]), "+f"(c[2]), "+f"(c[3])
        : "r"(a[0]), "r"(a[1]), "r"(a[2]), "r"(a[3]), "r"(b0), "r"(b1));
}

// pack two floats into bf16x2 (f0 -> low), residual into *lo
__device__ __forceinline__ uint32_t pack_split(float f0, float f1, uint32_t* lo) {
    __nv_bfloat16 h0 = __float2bfloat16_rn(f0);
    __nv_bfloat16 h1 = __float2bfloat16_rn(f1);
    float r0 = f0 - __bfloat162float(h0);
    float r1 = f1 - __bfloat162float(h1);
    __nv_bfloat162 hh(h0, h1);
    __nv_bfloat162 ll(__float2bfloat16_rn(r0), __float2bfloat16_rn(r1));
    *lo = *(uint32_t*)&ll;
    return *(uint32_t*)&hh;
}

// exact-ish tanh via exp: err ~ 1e-6 rel (vs tanh.approx 5e-4 — too coarse)
__device__ __forceinline__ float fast_tanh(float x) {
    float ax = fabsf(x);
    float e = __expf(-2.0f * ax);
    float t = __fdividef(1.0f - e, 1.0f + e);
    return copysignf(t, x);
}

// =================== split fp32 -> (bf16 hi, bf16 lo) =======================
__global__ __launch_bounds__(256)
void split_bf16(const float* __restrict__ in, __nv_bfloat16* __restrict__ hi,
                __nv_bfloat16* __restrict__ lo, int n4) {
    int i = blockIdx.x * blockDim.x + threadIdx.x;
    if (i >= n4) return;
    float4 v = ((const float4*)in)[i];
    __nv_bfloat16 h0 = __float2bfloat16_rn(v.x);
    __nv_bfloat16 h1 = __float2bfloat16_rn(v.y);
    __nv_bfloat16 h2 = __float2bfloat16_rn(v.z);
    __nv_bfloat16 h3 = __float2bfloat16_rn(v.w);
    __nv_bfloat16 l0 = __float2bfloat16_rn(v.x - __bfloat162float(h0));
    __nv_bfloat16 l1 = __float2bfloat16_rn(v.y - __bfloat162float(h1));
    __nv_bfloat16 l2 = __float2bfloat16_rn(v.z - __bfloat162float(h2));
    __nv_bfloat16 l3 = __float2bfloat16_rn(v.w - __bfloat162float(h3));
    __nv_bfloat162* hp = (__nv_bfloat162*)hi;
    __nv_bfloat162* lp = (__nv_bfloat162*)lo;
    hp[2*i]   = __nv_bfloat162(h0, h1);
    hp[2*i+1] = __nv_bfloat162(h2, h3);
    lp[2*i]   = __nv_bfloat162(l0, l1);
    lp[2*i+1] = __nv_bfloat162(l2, l3);
}

// ============== mma.sync bf16 GEMM: C[M,N] = A[M,K] @ B[N,K]^T ==============
// 3xBF16 split: C = Ah*Bh + Ah*Bl + Al*Bh (error ~ eps^2 ~ 1e-5).
#define BM 128
#define BN 128
#define BK 32
#define NKC (DMODEL / BK)
#define LDT 40
#define TILE_B (BM * LDT * 2)
#define STAGE_B (4 * TILE_B)
#define GEMM_SMEM (2 * STAGE_B)

__device__ __forceinline__ void load_stage(uint32_t sb, int buf,
                                           const __nv_bfloat16* __restrict__ Ah,
                                           const __nv_bfloat16* __restrict__ Al,
                                           const __nv_bfloat16* __restrict__ Bh,
                                           const __nv_bfloat16* __restrict__ Bl,
                                           int m0, int n0, int kc, int tid) {
    const uint32_t st = sb + buf * STAGE_B;
    const __nv_bfloat16* srcs[4] = {
        Ah + (size_t)m0 * DMODEL + kc * BK,
        Al + (size_t)m0 * DMODEL + kc * BK,
        Bh + (size_t)n0 * DMODEL + kc * BK,
        Bl + (size_t)n0 * DMODEL + kc * BK };
    #pragma unroll
    for (int t = 0; t < 4; t++) {
        #pragma unroll
        for (int it = 0; it < 2; it++) {
            int idx = tid + it * 256;
            int r = idx >> 2;
            int ch = idx & 3;
            const __nv_bfloat16* g = srcs[t] + (size_t)r * DMODEL + ch * 8;
            uint32_t d = st + t * TILE_B + r * (LDT * 2) + ch * 16;
            CP_ASYNC16(d, g);
        }
    }
}

__global__ __launch_bounds__(256)
void gemm_mma(const __nv_bfloat16* __restrict__ Ah, const __nv_bfloat16* __restrict__ Al,
              const __nv_bfloat16* __restrict__ Bh, const __nv_bfloat16* __restrict__ Bl,
              float* __restrict__ C, int M, int N) {
    extern __shared__ char smem[];
    const uint32_t sb = smem_u32(smem);
    const int tid = threadIdx.x;
    const int wid = tid >> 5;
    const int lane = tid & 31;
    const int wm = wid & 3;
    const int wn = wid >> 2;
    const int m0 = blockIdx.y * BM;
    const int n0 = blockIdx.x * BN;

    float acc[2][8][4];
    #pragma unroll
    for (int i = 0; i < 2; i++)
        #pragma unroll
        for (int j = 0; j < 8; j++)
            #pragma unroll
            for (int k = 0; k < 4; k++) acc[i][j][k] = 0.f;

    load_stage(sb, 0, Ah, Al, Bh, Bl, m0, n0, 0, tid);
    CP_COMMIT();

    const int lrow = lane & 15;
    const int lcol = (lane >> 4) * 16;

    for (int kc = 0; kc < NKC; kc++) {
        if (kc + 1 < NKC) {
            load_stage(sb, (kc + 1) & 1, Ah, Al, Bh, Bl, m0, n0, kc + 1, tid);
            CP_COMMIT();
            CP_WAIT(1);
        } else {
            CP_WAIT(0);
        }
        __syncthreads();

        const uint32_t st = sb + (kc & 1) * STAGE_B;
        const uint32_t aoff = st;
        const uint32_t boff = st + 2 * TILE_B;

        #pragma unroll
        for (int ks = 0; ks < 2; ks++) {
            uint32_t ah[2][4], al[2][4], bh[4][4], bl[4][4];
            #pragma unroll
            for (int mi = 0; mi < 2; mi++) {
                uint32_t ra = aoff + (uint32_t)(wm * 32 + mi * 16 + lrow) * (LDT * 2)
                            + ks * 32 + lcol;
                LDSM_X4(ah[mi][0], ah[mi][1], ah[mi][2], ah[mi][3], ra);
                LDSM_X4(al[mi][0], al[mi][1], al[mi][2], al[mi][3], ra + TILE_B);
            }
            #pragma unroll
            for (int ni = 0; ni < 4; ni++) {
                uint32_t rb = boff + (uint32_t)(wn * 64 + ni * 16 + lrow) * (LDT * 2)
                            + ks * 32 + lcol;
                LDSM_X4(bh[ni][0], bh[ni][1], bh[ni][2], bh[ni][3], rb);
                LDSM_X4(bl[ni][0], bl[ni][1], bl[ni][2], bl[ni][3], rb + TILE_B);
            }
            #pragma unroll
            for (int mi = 0; mi < 2; mi++) {
                #pragma unroll
                for (int nj = 0; nj < 8; nj++) {
                    const int ni = nj >> 1, hh = nj & 1;
                    mma16816(acc[mi][nj], ah[mi], bh[ni][hh], bh[ni][hh + 2]);
                    mma16816(acc[mi][nj], ah[mi], bl[ni][hh], bl[ni][hh + 2]);
                    mma16816(acc[mi][nj], al[mi], bh[ni][hh], bh[ni][hh + 2]);
                }
            }
        }
        __syncthreads();
    }

    const int mbase = m0 + wm * 32;
    const int nbase = n0 + wn * 64;
    #pragma unroll
    for (int mi = 0; mi < 2; mi++) {
        #pragma unroll
        for (int nj = 0; nj < 8; nj++) {
            int r = mbase + mi * 16 + (lane >> 2);
            int c = nbase + nj * 8 + (lane & 3) * 2;
            *(float2*)&C[(size_t)r * N + c] =
                make_float2(acc[mi][nj][0], acc[mi][nj][1]);
            *(float2*)&C[(size_t)(r + 8) * N + c] =
                make_float2(acc[mi][nj][2], acc[mi][nj][3]);
        }
    }
}

// ---------- fused RMSNorm + RoPE -> split bf16 hi/lo (warp per head) --------
// Reference quirk: RoPE on (B,H,T,D) with n = shape[1] == N_HEADS ->
// rope table indexed by HEAD index, broadcast over time.
__global__ __launch_bounds__(128)
void norm_rope_split(const float* __restrict__ in,
                     __nv_bfloat16* __restrict__ oh, __nv_bfloat16* __restrict__ ol,
                     const float* __restrict__ w,
                     const float* __restrict__ cs, const float* __restrict__ sn) {
    const int warp = threadIdx.x >> 5;
    const int lane = threadIdx.x & 31;
    const int flat = blockIdx.x * 4 + warp;
    const int row = flat >> 4;
    const int h = flat & 15;

    const size_t idx = (size_t)row * DMODEL + h * DHEAD + lane * 4;
    float4 v = *(const float4*)(in + idx);

    float ss = v.x * v.x + v.y * v.y + v.z * v.z + v.w * v.w;
    #pragma unroll
    for (int o = 16; o > 0; o >>= 1) ss += __shfl_xor_sync(0xffffffffu, ss, o);
    float r = rsqrtf(ss * (1.0f / DHEAD) + 1e-6f);

    float4 wv = *(const float4*)(w + lane * 4);
    float x0 = v.x * r * wv.x;
    float x1 = v.y * r * wv.y;
    float x2 = v.z * r * wv.z;
    float x3 = v.w * r * wv.w;

    int i0 = lane * 2;
    float c0 = cs[h * 64 + i0],     s0 = sn[h * 64 + i0];
    float c1 = cs[h * 64 + i0 + 1], s1 = sn[h * 64 + i0 + 1];

    float o0 = x0 * c0 - x1 * s0;
    float o1 = x0 * s0 + x1 * c0;
    float o2 = x2 * c1 - x3 * s1;
    float o3 = x2 * s1 + x3 * c1;

    __nv_bfloat16 h0 = __float2bfloat16_rn(o0), h1 = __float2bfloat16_rn(o1);
    __nv_bfloat16 h2 = __float2bfloat16_rn(o2), h3 = __float2bfloat16_rn(o3);
    __nv_bfloat162* hp = (__nv_bfloat162*)(oh + idx);
    hp[0] = __nv_bfloat162(h0, h1);
    hp[1] = __nv_bfloat162(h2, h3);
    __nv_bfloat162* lp = (__nv_bfloat162*)(ol + idx);
    lp[0] = __nv_bfloat162(__float2bfloat16_rn(o0 - __bfloat162float(h0)),
                           __float2bfloat16_rn(o1 - __bfloat162float(h1)));
    lp[1] = __nv_bfloat162(__float2bfloat16_rn(o2 - __bfloat162float(h2)),
                           __float2bfloat16_rn(o3 - __bfloat162float(h3)));
}

// ============== tensor-core flash attention (3x bf16 split) =================
// CTA: 128 Q rows, 8 warps (each owns m16 x full tile); key tiles of 64.
#define FQ 128
#define FK 64
#define QSTR 136                  // bf16 row stride (272 B): LDSM conflict-free
#define KVT_B (FK * QSTR * 2)     // 17408 per sub-tile
#define FSTG (4 * KVT_B)          // Kh,Kl,Vh,Vl = 69632
#define FSMEM (2 * FSTG)          // 139264

__device__ __forceinline__ void fa_load_kv(uint32_t st, int k0, size_t hb,
                                           const __nv_bfloat16* __restrict__ Kh,
                                           const __nv_bfloat16* __restrict__ Kl,
                                           const __nv_bfloat16* __restrict__ Vh,
                                           const __nv_bfloat16* __restrict__ Vl,
                                           int tid) {
    const __nv_bfloat16* srcs[4] = {
        Kh + hb + (size_t)k0 * DMODEL, Kl + hb + (size_t)k0 * DMODEL,
        Vh + hb + (size_t)k0 * DMODEL, Vl + hb + (size_t)k0 * DMODEL };
    #pragma unroll
    for (int t = 0; t < 4; t++) {
        #pragma unroll
        for (int it = 0; it < 4; it++) {
            int idx = tid + it * 256;   // 0..1023
            int r = idx >> 4;           // key row 0..63
            int ch = idx & 15;          // 16B chunk
            CP_ASYNC16(st + t * KVT_B + r * (QSTR * 2) + ch * 16,
                       srcs[t] + (size_t)r * DMODEL + ch * 8);
        }
    }
}

__global__ __launch_bounds__(256)
void flash_mma(const __nv_bfloat16* __restrict__ Qh, const __nv_bfloat16* __restrict__ Ql,
               const __nv_bfloat16* __restrict__ Kh, const __nv_bfloat16* __restrict__ Kl,
               const __nv_bfloat16* __restrict__ Vh, const __nv_bfloat16* __restrict__ Vl,
               float* __restrict__ O) {
    extern __shared__ char smem[];
    const uint32_t sb = smem_u32(smem);
    const int tid = threadIdx.x;
    const int wid = tid >> 5;
    const int lane = tid & 31;
    const int lrow = lane & 15;
    const int lcol = (lane >> 4) * 16;

    const int qtile = gridDim.x - 1 - blockIdx.x;   // heavy tiles first
    const int h = blockIdx.y;
    const int b = blockIdx.z;
    const int q0 = qtile * FQ;
    const size_t hb = (size_t)b * SEQ * DMODEL + (size_t)h * DHEAD;  // (b,h) base

    // ---- prologue: stage Q (hi+lo) into stage0 region, ldmatrix to regs ----
    {
        const __nv_bfloat16* qs[2] = { Qh + hb + (size_t)q0 * DMODEL,
                                       Ql + hb + (size_t)q0 * DMODEL };
        #pragma unroll
        for (int t = 0; t < 2; t++) {
            #pragma unroll
            for (int it = 0; it < 8; it++) {
                int idx = tid + it * 256;   // 0..2047
                int r = idx >> 4;           // 0..127
                int ch = idx & 15;
                CP_ASYNC16(sb + t * (FQ * QSTR * 2) + r * (QSTR * 2) + ch * 16,
                           qs[t] + (size_t)r * DMODEL + ch * 8);
            }
        }
        CP_COMMIT();
        CP_WAIT(0);
        __syncthreads();
    }

    uint32_t qfh[8][4], qfl[8][4];
    #pragma unroll
    for (int ks = 0; ks < 8; ks++) {
        uint32_t ra = sb + (uint32_t)(wid * 16 + lrow) * (QSTR * 2) + ks * 32 + lcol;
        LDSM_X4(qfh[ks][0], qfh[ks][1], qfh[ks][2], qfh[ks][3], ra);
        LDSM_X4(qfl[ks][0], qfl[ks][1], qfl[ks][2], qfl[ks][3],
                ra + FQ * QSTR * 2);
    }
    __syncthreads();   // everyone done reading Q smem

    // state
    float m_r[2] = { -1e30f, -1e30f };
    float l_r[2] = { 0.f, 0.f };
    float oacc[16][4];
    #pragma unroll
    for (int i = 0; i < 16; i++)
        #pragma unroll
        for (int j = 0; j < 4; j++) oacc[i][j] = 0.f;

    const int ntiles = 2 * qtile + 2;

    // load tile 0 into stage 0
    fa_load_kv(sb, 0, hb, Kh, Kl, Vh, Vl, tid);
    CP_COMMIT();

    const int qg0 = q0 + wid * 16 + (lane >> 2);

    for (int kt = 0; kt < ntiles; kt++) {
        if (kt + 1 < ntiles) {
            fa_load_kv(sb + ((kt + 1) & 1) * FSTG, (kt + 1) * FK, hb,
                       Kh, Kl, Vh, Vl, tid);
            CP_COMMIT();
            CP_WAIT(1);
        } else {
            CP_WAIT(0);
        }
        __syncthreads();

        const uint32_t st = sb + (kt & 1) * FSTG;
        const int k0 = kt * FK;

        // ---- S = Q K^T (3-term split) ----
        float sacc[8][4];
        #pragma unroll
        for (int n = 0; n < 8; n++)
            #pragma unroll
            for (int j = 0; j < 4; j++) sacc[n][j] = 0.f;

        #pragma unroll
        for (int ks = 0; ks < 8; ks++) {
            uint32_t kb[4][4];
            #pragma unroll
            for (int ni = 0; ni < 4; ni++) {
                uint32_t rb = st + (uint32_t)(ni * 16 + lrow) * (QSTR * 2)
                            + ks * 32 + lcol;
                LDSM_X4(kb[ni][0], kb[ni][1], kb[ni][2], kb[ni][3], rb);
            }
            #pragma unroll
            for (int n = 0; n < 8; n++) {
                const int ni = n >> 1, hh = n & 1;
                mma16816(sacc[n], qfh[ks], kb[ni][hh], kb[ni][hh + 2]);
                mma16816(sacc[n], qfl[ks], kb[ni][hh], kb[ni][hh + 2]);
            }
            #pragma unroll
            for (int ni = 0; ni < 4; ni++) {
                uint32_t rb = st + KVT_B + (uint32_t)(ni * 16 + lrow) * (QSTR * 2)
                            + ks * 32 + lcol;
                LDSM_X4(kb[ni][0], kb[ni][1], kb[ni][2], kb[ni][3], rb);
            }
            #pragma unroll
            for (int n = 0; n < 8; n++) {
                const int ni = n >> 1, hh = n & 1;
                mma16816(sacc[n], qfh[ks], kb[ni][hh], kb[ni][hh + 2]);
            }
        }

        // ---- softcap + causal + online softmax (per row-half) ----
        const bool needmask = (k0 + FK - 1) > (q0 + wid * 16);
        #pragma unroll
        for (int half = 0; half < 2; half++) {
            const int qg = qg0 + half * 8;
            float mx = -1e30f;
            #pragma unroll
            for (int n = 0; n < 8; n++) {
                #pragma unroll
                for (int e = 0; e < 2; e++) {
                    float s = sacc[n][half * 2 + e];
                    float v = SOFTCAP * fast_tanh(s * (ATTN_SCALE / SOFTCAP));
                    if (needmask) {
                        int kg = k0 + n * 8 + ((lane & 3) << 1) + e;
                        if (kg > qg) v = -1e30f;
                    }
                    sacc[n][half * 2 + e] = v;
                    mx = fmaxf(mx, v);
                }
            }
            mx = fmaxf(mx, __shfl_xor_sync(0xffffffffu, mx, 1));
            mx = fmaxf(mx, __shfl_xor_sync(0xffffffffu, mx, 2));
            float mnew = fmaxf(m_r[half], mx);
            float alpha = __expf(m_r[half] - mnew);
            m_r[half] = mnew;
            float ls = 0.f;
            #pragma unroll
            for (int n = 0; n < 8; n++) {
                #pragma unroll
                for (int e = 0; e < 2; e++) {
                    float p = __expf(sacc[n][half * 2 + e] - mnew);
                    sacc[n][half * 2 + e] = p;
                    ls += p;
                }
            }
            ls += __shfl_xor_sync(0xffffffffu, ls, 1);
            ls += __shfl_xor_sync(0xffffffffu, ls, 2);
            l_r[half] = l_r[half] * alpha + ls;
            #pragma unroll
            for (int dt = 0; dt < 16; dt++) {
                oacc[dt][half * 2 + 0] *= alpha;
                oacc[dt][half * 2 + 1] *= alpha;
            }
        }

        // ---- O += P V (P split in registers; V from smem via ldmatrix.trans)
        #pragma unroll
        for (int t = 0; t < 4; t++) {
            uint32_t pha[4], pla[4];
            pha[0] = pack_split(sacc[2*t][0],   sacc[2*t][1],   &pla[0]);
            pha[1] = pack_split(sacc[2*t][2],   sacc[2*t][3],   &pla[1]);
            pha[2] = pack_split(sacc[2*t+1][0], sacc[2*t+1][1], &pla[2]);
            pha[3] = pack_split(sacc[2*t+1][2], sacc[2*t+1][3], &pla[3]);
            #pragma unroll
            for (int dt = 0; dt < 8; dt++) {
                uint32_t vh4[4], vl4[4];
                uint32_t va = st + 2 * KVT_B
                            + (uint32_t)(t * 16 + lrow) * (QSTR * 2) + dt * 32 + lcol;
                LDSM_X4_T(vh4[0], vh4[1], vh4[2], vh4[3], va);
                LDSM_X4_T(vl4[0], vl4[1], vl4[2], vl4[3], va + KVT_B);
                mma16816(oacc[2*dt],     pha, vh4[0], vh4[1]);
                mma16816(oacc[2*dt],     pha, vl4[0], vl4[1]);
                mma16816(oacc[2*dt],     pla, vh4[0], vh4[1]);
                mma16816(oacc[2*dt+1],   pha, vh4[2], vh4[3]);
                mma16816(oacc[2*dt+1],   pha, vl4[2], vl4[3]);
                mma16816(oacc[2*dt+1],   pla, vh4[2], vh4[3]);
            }
        }
        __syncthreads();   // all warps done with this stage before overwrite
    }

    // ---- epilogue ----
    float inv0 = 1.0f / l_r[0];
    float inv1 = 1.0f / l_r[1];
    #pragma unroll
    for (int dt = 0; dt < 16; dt++) {
        size_t r0 = hb + (size_t)qg0 * DMODEL + dt * 8 + (lane & 3) * 2;
        *(float2*)&O[r0] = make_float2(oacc[dt][0] * inv0, oacc[dt][1] * inv0);
        *(float2*)&O[r0 + 8 * DMODEL] =
            make_float2(oacc[dt][2] * inv1, oacc[dt][3] * inv1);
    }
}

// ----------------------------- launch -------------------------------------
extern "C" void kernel_launch(void* const* d_in, const int* in_sizes, int n_in,
                              void* d_out, int out_size) {
    const float* x        = (const float*)d_in[0];
    const float* wq       = (const float*)d_in[1];
    const float* wk       = (const float*)d_in[2];
    const float* wv       = (const float*)d_in[3];
    const float* wo       = (const float*)d_in[4];
    const float* q_norm_w = (const float*)d_in[5];
    const float* k_norm_w = (const float*)d_in[6];
    const float* rope_cos = (const float*)d_in[7];
    const float* rope_sin = (const float*)d_in[8];
    float* out = (float*)d_out;

    float *qb, *kb, *vb, *ab;
    cudaGetSymbolAddress((void**)&qb, g_q);
    cudaGetSymbolAddress((void**)&kb, g_k);
    cudaGetSymbolAddress((void**)&vb, g_v);
    cudaGetSymbolAddress((void**)&ab, g_att);
    __nv_bfloat16 *xh, *xl, *ah, *al, *qh, *ql, *kh, *kl, *vh, *vl;
    __nv_bfloat16 *wqh, *wql, *wkh, *wkl, *wvh, *wvl, *woh, *wol;
    cudaGetSymbolAddress((void**)&xh, g_xh);   cudaGetSymbolAddress((void**)&xl, g_xl);
    cudaGetSymbolAddress((void**)&ah, g_ah);   cudaGetSymbolAddress((void**)&al, g_al);
    cudaGetSymbolAddress((void**)&qh, g_qh);   cudaGetSymbolAddress((void**)&ql, g_ql);
    cudaGetSymbolAddress((void**)&kh, g_kh);   cudaGetSymbolAddress((void**)&kl, g_kl);
    cudaGetSymbolAddress((void**)&vh, g_vh);   cudaGetSymbolAddress((void**)&vl, g_vl);
    cudaGetSymbolAddress((void**)&wqh, g_wqh); cudaGetSymbolAddress((void**)&wql, g_wql);
    cudaGetSymbolAddress((void**)&wkh, g_wkh); cudaGetSymbolAddress((void**)&wkl, g_wkl);
    cudaGetSymbolAddress((void**)&wvh, g_wvh); cudaGetSymbolAddress((void**)&wvl, g_wvl);
    cudaGetSymbolAddress((void**)&woh, g_woh); cudaGetSymbolAddress((void**)&wol, g_wol);

    cudaFuncSetAttribute(gemm_mma, cudaFuncAttributeMaxDynamicSharedMemorySize,
                         GEMM_SMEM);
    cudaFuncSetAttribute(flash_mma, cudaFuncAttributeMaxDynamicSharedMemorySize,
                         FSMEM);

    // split conversions
    const int NX4 = ROWS * DMODEL / 4;
    const int NW4 = DMODEL * DMODEL / 4;
    split_bf16<<<NX4 / 256, 256>>>(x,  xh,  xl,  NX4);
    split_bf16<<<NW4 / 256, 256>>>(wq, wqh, wql, NW4);
    split_bf16<<<NW4 / 256, 256>>>(wk, wkh, wkl, NW4);
    split_bf16<<<NW4 / 256, 256>>>(wv, wvh, wvl, NW4);
    split_bf16<<<NW4 / 256, 256>>>(wo, woh, wol, NW4);

    // QKV projections (HMMA)
    dim3 tgrid(DMODEL / BN, ROWS / BM);
    gemm_mma<<<tgrid, 256, GEMM_SMEM>>>(xh, xl, wqh, wql, qb, ROWS, DMODEL);
    gemm_mma<<<tgrid, 256, GEMM_SMEM>>>(xh, xl, wkh, wkl, kb, ROWS, DMODEL);
    gemm_mma<<<tgrid, 256, GEMM_SMEM>>>(xh, xl, wvh, wvl, vb, ROWS, DMODEL);

    // norm+rope, emitting split bf16 directly
    int nr_blocks = ROWS * NHEADS / 4;
    norm_rope_split<<<nr_blocks, 128>>>(qb, qh, ql, q_norm_w, rope_cos, rope_sin);
    norm_rope_split<<<nr_blocks, 128>>>(kb, kh, kl, k_norm_w, rope_cos, rope_sin);
    split_bf16<<<NX4 / 256, 256>>>(vb, vh, vl, NX4);

    // tensor-core flash attention
    dim3 fgrid(SEQ / FQ, NHEADS, BATCH);   // 16 x 16 x 2
    flash_mma<<<fgrid, 256, FSMEM>>>(qh, ql, kh, kl, vh, vl, ab);

    // output projection
    split_bf16<<<NX4 / 256, 256>>>(ab, ah, al, NX4);
    gemm_mma<<<tgrid, 256, GEMM_SMEM>>>(ah, al, woh, wol, out, ROWS, DMODEL);
}

// round 9
// speedup vs baseline: 2.6786x; 1.0010x over previous
#include <cuda_runtime.h>
#include <cuda_bf16.h>
#include <math.h>
#include <stdint.h>

// Problem constants
#define BATCH 2
#define SEQ 2048
#define DMODEL 2048
#define NHEADS 16
#define DHEAD 128
#define ROWS (BATCH*SEQ)          // 4096
#define SOFTCAP 50.0f
#define ATTN_SCALE 0.08838834764831845f  // 1/sqrt(128)

// ---------------- scratch (device globals; no allocation allowed) -----------
__device__ __nv_bfloat16 g_xh[ROWS * DMODEL];
__device__ __nv_bfloat16 g_xl[ROWS * DMODEL];
__device__ __nv_bfloat16 g_ah[ROWS * DMODEL];
__device__ __nv_bfloat16 g_al[ROWS * DMODEL];
__device__ __nv_bfloat16 g_qh[ROWS * DMODEL];
__device__ __nv_bfloat16 g_ql[ROWS * DMODEL];
__device__ __nv_bfloat16 g_kh[ROWS * DMODEL];
__device__ __nv_bfloat16 g_kl[ROWS * DMODEL];
__device__ __nv_bfloat16 g_vh[ROWS * DMODEL];
__device__ __nv_bfloat16 g_vl[ROWS * DMODEL];
__device__ __nv_bfloat16 g_wqh[DMODEL * DMODEL];
__device__ __nv_bfloat16 g_wql[DMODEL * DMODEL];
__device__ __nv_bfloat16 g_wkh[DMODEL * DMODEL];
__device__ __nv_bfloat16 g_wkl[DMODEL * DMODEL];
__device__ __nv_bfloat16 g_wvh[DMODEL * DMODEL];
__device__ __nv_bfloat16 g_wvl[DMODEL * DMODEL];
__device__ __nv_bfloat16 g_woh[DMODEL * DMODEL];
__device__ __nv_bfloat16 g_wol[DMODEL * DMODEL];

// ======================= PTX helpers (baseline PTX only!) ===================
// Harness compiles at compute_103 (no 'a'): tcgen05/TMEM unavailable.
// mma.sync / ldmatrix / cp.async are baseline and map to HMMA/LDSM/LDGSTS.
__device__ __forceinline__ uint32_t smem_u32(const void* p) {
    uint32_t a;
    asm("{ .reg .u64 t; cvta.to.shared.u64 t, %1; cvt.u32.u64 %0, t; }"
        : "=r"(a) : "l"(p));
    return a;
}
#define CP_ASYNC16(dst, src) \
    asm volatile("cp.async.cg.shared.global [%0], [%1], 16;" :: "r"(dst), "l"(src))
#define CP_COMMIT() asm volatile("cp.async.commit_group;" ::: "memory")
#define CP_WAIT(n)  asm volatile("cp.async.wait_group %0;" :: "n"(n) : "memory")

#define LDSM_X4(r0, r1, r2, r3, addr) \
    asm volatile("ldmatrix.sync.aligned.m8n8.x4.shared.b16 {%0,%1,%2,%3}, [%4];" \
        : "=r"(r0), "=r"(r1), "=r"(r2), "=r"(r3) : "r"(addr))
#define LDSM_X4_T(r0, r1, r2, r3, addr) \
    asm volatile("ldmatrix.sync.aligned.m8n8.x4.trans.shared.b16 {%0,%1,%2,%3}, [%4];" \
        : "=r"(r0), "=r"(r1), "=r"(r2), "=r"(r3) : "r"(addr))

__device__ __forceinline__ void mma16816(float* c, const uint32_t* a,
                                         uint32_t b0, uint32_t b1) {
    asm volatile("mma.sync.aligned.m16n8k16.row.col.f32.bf16.bf16.f32 "
        "{%0,%1,%2,%3}, {%4,%5,%6,%7}, {%8,%9}, {%0,%1,%2,%3};"
        : "+f"(c[0]), "+f"(c[1]), "+f"(c[2]), "+f"(c[3])
        : "r"(a[0]), "r"(a[1]), "r"(a[2]), "r"(a[3]), "r"(b0), "r"(b1));
}

// pack two floats into bf16x2 (f0 -> low), residual into *lo
__device__ __forceinline__ uint32_t pack_split(float f0, float f1, uint32_t* lo) {
    __nv_bfloat16 h0 = __float2bfloat16_rn(f0);
    __nv_bfloat16 h1 = __float2bfloat16_rn(f1);
    float r0 = f0 - __bfloat162float(h0);
    float r1 = f1 - __bfloat162float(h1);
    __nv_bfloat162 hh(h0, h1);
    __nv_bfloat162 ll(__float2bfloat16_rn(r0), __float2bfloat16_rn(r1));
    *lo = *(uint32_t*)&ll;
    return *(uint32_t*)&hh;
}

// exact-ish tanh via exp (tanh.approx is 5e-4 — too coarse)
__device__ __forceinline__ float fast_tanh(float x) {
    float ax = fabsf(x);
    float e = __expf(-2.0f * ax);
    float t = __fdividef(1.0f - e, 1.0f + e);
    return copysignf(t, x);
}

// =================== split fp32 -> (bf16 hi, bf16 lo) =======================
__global__ __launch_bounds__(256)
void split_bf16(const float* __restrict__ in, __nv_bfloat16* __restrict__ hi,
                __nv_bfloat16* __restrict__ lo, int n4) {
    int i = blockIdx.x * blockDim.x + threadIdx.x;
    if (i >= n4) return;
    float4 v = ((const float4*)in)[i];
    __nv_bfloat16 h0 = __float2bfloat16_rn(v.x);
    __nv_bfloat16 h1 = __float2bfloat16_rn(v.y);
    __nv_bfloat16 h2 = __float2bfloat16_rn(v.z);
    __nv_bfloat16 h3 = __float2bfloat16_rn(v.w);
    __nv_bfloat16 l0 = __float2bfloat16_rn(v.x - __bfloat162float(h0));
    __nv_bfloat16 l1 = __float2bfloat16_rn(v.y - __bfloat162float(h1));
    __nv_bfloat16 l2 = __float2bfloat16_rn(v.z - __bfloat162float(h2));
    __nv_bfloat16 l3 = __float2bfloat16_rn(v.w - __bfloat162float(h3));
    __nv_bfloat162* hp = (__nv_bfloat162*)hi;
    __nv_bfloat162* lp = (__nv_bfloat162*)lo;
    hp[2*i]   = __nv_bfloat162(h0, h1);
    hp[2*i+1] = __nv_bfloat162(h2, h3);
    lp[2*i]   = __nv_bfloat162(l0, l1);
    lp[2*i+1] = __nv_bfloat162(l2, l3);
}

// ============== mma.sync bf16 GEMM core (3x bf16 split) =====================
#define BM 128
#define BN 128
#define BK 32
#define NKC (DMODEL / BK)
#define LDT 40
#define TILE_B (BM * LDT * 2)
#define STAGE_B (4 * TILE_B)
#define GEMM_SMEM (2 * STAGE_B)

__device__ __forceinline__ void load_stage(uint32_t sb, int buf,
                                           const __nv_bfloat16* __restrict__ Ah,
                                           const __nv_bfloat16* __restrict__ Al,
                                           const __nv_bfloat16* __restrict__ Bh,
                                           const __nv_bfloat16* __restrict__ Bl,
                                           int m0, int n0, int kc, int tid) {
    const uint32_t st = sb + buf * STAGE_B;
    const __nv_bfloat16* srcs[4] = {
        Ah + (size_t)m0 * DMODEL + kc * BK,
        Al + (size_t)m0 * DMODEL + kc * BK,
        Bh + (size_t)n0 * DMODEL + kc * BK,
        Bl + (size_t)n0 * DMODEL + kc * BK };
    #pragma unroll
    for (int t = 0; t < 4; t++) {
        #pragma unroll
        for (int it = 0; it < 2; it++) {
            int idx = tid + it * 256;
            int r = idx >> 2;
            int ch = idx & 3;
            const __nv_bfloat16* g = srcs[t] + (size_t)r * DMODEL + ch * 8;
            uint32_t d = st + t * TILE_B + r * (LDT * 2) + ch * 16;
            CP_ASYNC16(d, g);
        }
    }
}

// mainloop shared by both GEMM kernels; leaves results in acc[2][8][4]
__device__ __forceinline__ void gemm_mainloop(
        uint32_t sb, const __nv_bfloat16* __restrict__ Ah,
        const __nv_bfloat16* __restrict__ Al,
        const __nv_bfloat16* __restrict__ Bh,
        const __nv_bfloat16* __restrict__ Bl,
        int m0, int n0, int tid, int wm, int wn, int lane,
        float acc[2][8][4]) {
    #pragma unroll
    for (int i = 0; i < 2; i++)
        #pragma unroll
        for (int j = 0; j < 8; j++)
            #pragma unroll
            for (int k = 0; k < 4; k++) acc[i][j][k] = 0.f;

    load_stage(sb, 0, Ah, Al, Bh, Bl, m0, n0, 0, tid);
    CP_COMMIT();

    const int lrow = lane & 15;
    const int lcol = (lane >> 4) * 16;

    for (int kc = 0; kc < NKC; kc++) {
        if (kc + 1 < NKC) {
            load_stage(sb, (kc + 1) & 1, Ah, Al, Bh, Bl, m0, n0, kc + 1, tid);
            CP_COMMIT();
            CP_WAIT(1);
        } else {
            CP_WAIT(0);
        }
        __syncthreads();

        const uint32_t st = sb + (kc & 1) * STAGE_B;
        const uint32_t aoff = st;
        const uint32_t boff = st + 2 * TILE_B;

        #pragma unroll
        for (int ks = 0; ks < 2; ks++) {
            uint32_t ah[2][4], al[2][4], bh[4][4], bl[4][4];
            #pragma unroll
            for (int mi = 0; mi < 2; mi++) {
                uint32_t ra = aoff + (uint32_t)(wm * 32 + mi * 16 + lrow) * (LDT * 2)
                            + ks * 32 + lcol;
                LDSM_X4(ah[mi][0], ah[mi][1], ah[mi][2], ah[mi][3], ra);
                LDSM_X4(al[mi][0], al[mi][1], al[mi][2], al[mi][3], ra + TILE_B);
            }
            #pragma unroll
            for (int ni = 0; ni < 4; ni++) {
                uint32_t rb = boff + (uint32_t)(wn * 64 + ni * 16 + lrow) * (LDT * 2)
                            + ks * 32 + lcol;
                LDSM_X4(bh[ni][0], bh[ni][1], bh[ni][2], bh[ni][3], rb);
                LDSM_X4(bl[ni][0], bl[ni][1], bl[ni][2], bl[ni][3], rb + TILE_B);
            }
            #pragma unroll
            for (int mi = 0; mi < 2; mi++) {
                #pragma unroll
                for (int nj = 0; nj < 8; nj++) {
                    const int ni = nj >> 1, hh = nj & 1;
                    mma16816(acc[mi][nj], ah[mi], bh[ni][hh], bh[ni][hh + 2]);
                    mma16816(acc[mi][nj], ah[mi], bl[ni][hh], bl[ni][hh + 2]);
                    mma16816(acc[mi][nj], al[mi], bh[ni][hh], bh[ni][hh + 2]);
                }
            }
        }
        __syncthreads();
    }
}

// ---- fused QKV GEMM: per-CTA n-tile == one full head (BN == DHEAD) --------
// Epilogue applies RMSNorm + head-indexed RoPE (reference quirk: rope table
// indexed by HEAD, broadcast over time) for Q/K sections, then splits to
// bf16 hi/lo.  V section only splits.
__global__ __launch_bounds__(256)
void gemm_qkv(const __nv_bfloat16* __restrict__ xh, const __nv_bfloat16* __restrict__ xl,
              const __nv_bfloat16* __restrict__ wqh, const __nv_bfloat16* __restrict__ wql,
              const __nv_bfloat16* __restrict__ wkh, const __nv_bfloat16* __restrict__ wkl,
              const __nv_bfloat16* __restrict__ wvh, const __nv_bfloat16* __restrict__ wvl,
              __nv_bfloat16* __restrict__ qh, __nv_bfloat16* __restrict__ ql,
              __nv_bfloat16* __restrict__ kh, __nv_bfloat16* __restrict__ kl,
              __nv_bfloat16* __restrict__ vh, __nv_bfloat16* __restrict__ vl,
              const float* __restrict__ qnw, const float* __restrict__ knw,
              const float* __restrict__ cs, const float* __restrict__ sn) {
    extern __shared__ char smem[];
    const uint32_t sb = smem_u32(smem);
    const int tid = threadIdx.x;
    const int wid = tid >> 5;
    const int lane = tid & 31;
    const int wm = wid & 3;
    const int wn = wid >> 2;
    const int m0 = blockIdx.y * BM;
    const int sec = blockIdx.x >> 4;    // 0=Q, 1=K, 2=V
    const int h = blockIdx.x & 15;
    const int n0 = h * DHEAD;

    const __nv_bfloat16 *Bh_, *Bl_;
    __nv_bfloat16 *Oh_, *Ol_;
    const float* nw;
    if (sec == 0)      { Bh_ = wqh; Bl_ = wql; Oh_ = qh; Ol_ = ql; nw = qnw; }
    else if (sec == 1) { Bh_ = wkh; Bl_ = wkl; Oh_ = kh; Ol_ = kl; nw = knw; }
    else               { Bh_ = wvh; Bl_ = wvl; Oh_ = vh; Ol_ = vl; nw = qnw; }

    float acc[2][8][4];
    gemm_mainloop(sb, xh, xl, Bh_, Bl_, m0, n0, tid, wm, wn, lane, acc);

    // ---- fused epilogue ----
    float rinv[2][2] = {{1.f, 1.f}, {1.f, 1.f}};
    if (sec < 2) {
        float* rss = (float*)smem;           // [2][128], reuses dead stage mem
        float ss[2][2];
        #pragma unroll
        for (int mi = 0; mi < 2; mi++) {
            #pragma unroll
            for (int p = 0; p < 2; p++) {
                float s = 0.f;
                #pragma unroll
                for (int nj = 0; nj < 8; nj++) {
                    float a0 = acc[mi][nj][2*p], a1 = acc[mi][nj][2*p+1];
                    s += a0 * a0 + a1 * a1;
                }
                s += __shfl_xor_sync(0xffffffffu, s, 1);
                s += __shfl_xor_sync(0xffffffffu, s, 2);
                ss[mi][p] = s;
            }
        }
        if ((lane & 3) == 0) {
            #pragma unroll
            for (int mi = 0; mi < 2; mi++)
                #pragma unroll
                for (int p = 0; p < 2; p++)
                    rss[wn * 128 + wm * 32 + mi * 16 + p * 8 + (lane >> 2)] = ss[mi][p];
        }
        __syncthreads();
        #pragma unroll
        for (int mi = 0; mi < 2; mi++) {
            #pragma unroll
            for (int p = 0; p < 2; p++) {
                int r = wm * 32 + mi * 16 + p * 8 + (lane >> 2);
                float tot = rss[r] + rss[128 + r];
                rinv[mi][p] = rsqrtf(tot * (1.0f / DHEAD) + 1e-6f);
            }
        }
    }

    #pragma unroll
    for (int mi = 0; mi < 2; mi++) {
        #pragma unroll
        for (int p = 0; p < 2; p++) {
            const int row = m0 + wm * 32 + mi * 16 + p * 8 + (lane >> 2);
            #pragma unroll
            for (int nj = 0; nj < 8; nj++) {
                float v0 = acc[mi][nj][2*p], v1 = acc[mi][nj][2*p+1];
                const int c = wn * 64 + nj * 8 + (lane & 3) * 2;   // col in head
                if (sec < 2) {
                    float r = rinv[mi][p];
                    v0 *= r * nw[c];
                    v1 *= r * nw[c + 1];
                    const int pi = c >> 1;
                    float co = cs[h * 64 + pi], si = sn[h * 64 + pi];
                    float o0 = v0 * co - v1 * si;
                    float o1 = v0 * si + v1 * co;
                    v0 = o0; v1 = o1;
                }
                uint32_t lo;
                uint32_t hi = pack_split(v0, v1, &lo);
                size_t off = (size_t)row * DMODEL + n0 + c;
                *(uint32_t*)(Oh_ + off) = hi;
                *(uint32_t*)(Ol_ + off) = lo;
            }
        }
    }
}

// ---- output projection GEMM: plain fp32 epilogue --------------------------
__global__ __launch_bounds__(256)
void gemm_out(const __nv_bfloat16* __restrict__ Ah, const __nv_bfloat16* __restrict__ Al,
              const __nv_bfloat16* __restrict__ Bh, const __nv_bfloat16* __restrict__ Bl,
              float* __restrict__ C) {
    extern __shared__ char smem[];
    const uint32_t sb = smem_u32(smem);
    const int tid = threadIdx.x;
    const int wid = tid >> 5;
    const int lane = tid & 31;
    const int wm = wid & 3;
    const int wn = wid >> 2;
    const int m0 = blockIdx.y * BM;
    const int n0 = blockIdx.x * BN;

    float acc[2][8][4];
    gemm_mainloop(sb, Ah, Al, Bh, Bl, m0, n0, tid, wm, wn, lane, acc);

    const int mbase = m0 + wm * 32;
    const int nbase = n0 + wn * 64;
    #pragma unroll
    for (int mi = 0; mi < 2; mi++) {
        #pragma unroll
        for (int nj = 0; nj < 8; nj++) {
            int r = mbase + mi * 16 + (lane >> 2);
            int c = nbase + nj * 8 + (lane & 3) * 2;
            *(float2*)&C[(size_t)r * DMODEL + c] =
                make_float2(acc[mi][nj][0], acc[mi][nj][1]);
            *(float2*)&C[(size_t)(r + 8) * DMODEL + c] =
                make_float2(acc[mi][nj][2], acc[mi][nj][3]);
        }
    }
}

// ============== tensor-core flash attention (3x bf16 split) =================
#define FQ 128
#define FK 64
#define QSTR 136                  // bf16 row stride (272 B): LDSM conflict-free
#define KVT_B (FK * QSTR * 2)     // 17408 per sub-tile
#define FSTG (4 * KVT_B)          // Kh,Kl,Vh,Vl = 69632
#define FSMEM (2 * FSTG)          // 139264

__device__ __forceinline__ void fa_load_kv(uint32_t st, int k0, size_t hb,
                                           const __nv_bfloat16* __restrict__ Kh,
                                           const __nv_bfloat16* __restrict__ Kl,
                                           const __nv_bfloat16* __restrict__ Vh,
                                           const __nv_bfloat16* __restrict__ Vl,
                                           int tid) {
    const __nv_bfloat16* srcs[4] = {
        Kh + hb + (size_t)k0 * DMODEL, Kl + hb + (size_t)k0 * DMODEL,
        Vh + hb + (size_t)k0 * DMODEL, Vl + hb + (size_t)k0 * DMODEL };
    #pragma unroll
    for (int t = 0; t < 4; t++) {
        #pragma unroll
        for (int it = 0; it < 4; it++) {
            int idx = tid + it * 256;
            int r = idx >> 4;
            int ch = idx & 15;
            CP_ASYNC16(st + t * KVT_B + r * (QSTR * 2) + ch * 16,
                       srcs[t] + (size_t)r * DMODEL + ch * 8);
        }
    }
}

__global__ __launch_bounds__(256)
void flash_mma(const __nv_bfloat16* __restrict__ Qh, const __nv_bfloat16* __restrict__ Ql,
               const __nv_bfloat16* __restrict__ Kh, const __nv_bfloat16* __restrict__ Kl,
               const __nv_bfloat16* __restrict__ Vh, const __nv_bfloat16* __restrict__ Vl,
               __nv_bfloat16* __restrict__ Oh, __nv_bfloat16* __restrict__ Ol) {
    extern __shared__ char smem[];
    const uint32_t sb = smem_u32(smem);
    const int tid = threadIdx.x;
    const int wid = tid >> 5;
    const int lane = tid & 31;
    const int lrow = lane & 15;
    const int lcol = (lane >> 4) * 16;

    const int qtile = gridDim.x - 1 - blockIdx.x;
    const int h = blockIdx.y;
    const int b = blockIdx.z;
    const int q0 = qtile * FQ;
    const size_t hb = (size_t)b * SEQ * DMODEL + (size_t)h * DHEAD;

    // ---- prologue: stage Q (hi+lo), ldmatrix to regs ----
    {
        const __nv_bfloat16* qs[2] = { Qh + hb + (size_t)q0 * DMODEL,
                                       Ql + hb + (size_t)q0 * DMODEL };
        #pragma unroll
        for (int t = 0; t < 2; t++) {
            #pragma unroll
            for (int it = 0; it < 8; it++) {
                int idx = tid + it * 256;
                int r = idx >> 4;
                int ch = idx & 15;
                CP_ASYNC16(sb + t * (FQ * QSTR * 2) + r * (QSTR * 2) + ch * 16,
                           qs[t] + (size_t)r * DMODEL + ch * 8);
            }
        }
        CP_COMMIT();
        CP_WAIT(0);
        __syncthreads();
    }

    uint32_t qfh[8][4], qfl[8][4];
    #pragma unroll
    for (int ks = 0; ks < 8; ks++) {
        uint32_t ra = sb + (uint32_t)(wid * 16 + lrow) * (QSTR * 2) + ks * 32 + lcol;
        LDSM_X4(qfh[ks][0], qfh[ks][1], qfh[ks][2], qfh[ks][3], ra);
        LDSM_X4(qfl[ks][0], qfl[ks][1], qfl[ks][2], qfl[ks][3],
                ra + FQ * QSTR * 2);
    }
    __syncthreads();

    float m_r[2] = { -1e30f, -1e30f };
    float l_r[2] = { 0.f, 0.f };
    float oacc[16][4];
    #pragma unroll
    for (int i = 0; i < 16; i++)
        #pragma unroll
        for (int j = 0; j < 4; j++) oacc[i][j] = 0.f;

    const int ntiles = 2 * qtile + 2;

    fa_load_kv(sb, 0, hb, Kh, Kl, Vh, Vl, tid);
    CP_COMMIT();

    const int qg0 = q0 + wid * 16 + (lane >> 2);

    for (int kt = 0; kt < ntiles; kt++) {
        if (kt + 1 < ntiles) {
            fa_load_kv(sb + ((kt + 1) & 1) * FSTG, (kt + 1) * FK, hb,
                       Kh, Kl, Vh, Vl, tid);
            CP_COMMIT();
            CP_WAIT(1);
        } else {
            CP_WAIT(0);
        }
        __syncthreads();

        const uint32_t st = sb + (kt & 1) * FSTG;
        const int k0 = kt * FK;

        // ---- S = Q K^T (3-term split) ----
        float sacc[8][4];
        #pragma unroll
        for (int n = 0; n < 8; n++)
            #pragma unroll
            for (int j = 0; j < 4; j++) sacc[n][j] = 0.f;

        #pragma unroll
        for (int ks = 0; ks < 8; ks++) {
            uint32_t kb[4][4];
            #pragma unroll
            for (int ni = 0; ni < 4; ni++) {
                uint32_t rb = st + (uint32_t)(ni * 16 + lrow) * (QSTR * 2)
                            + ks * 32 + lcol;
                LDSM_X4(kb[ni][0], kb[ni][1], kb[ni][2], kb[ni][3], rb);
            }
            #pragma unroll
            for (int n = 0; n < 8; n++) {
                const int ni = n >> 1, hh = n & 1;
                mma16816(sacc[n], qfh[ks], kb[ni][hh], kb[ni][hh + 2]);
                mma16816(sacc[n], qfl[ks], kb[ni][hh], kb[ni][hh + 2]);
            }
            #pragma unroll
            for (int ni = 0; ni < 4; ni++) {
                uint32_t rb = st + KVT_B + (uint32_t)(ni * 16 + lrow) * (QSTR * 2)
                            + ks * 32 + lcol;
                LDSM_X4(kb[ni][0], kb[ni][1], kb[ni][2], kb[ni][3], rb);
            }
            #pragma unroll
            for (int n = 0; n < 8; n++) {
                const int ni = n >> 1, hh = n & 1;
                mma16816(sacc[n], qfh[ks], kb[ni][hh], kb[ni][hh + 2]);
            }
        }

        // ---- softcap + causal + online softmax ----
        const bool needmask = (k0 + FK - 1) > (q0 + wid * 16);
        #pragma unroll
        for (int half = 0; half < 2; half++) {
            const int qg = qg0 + half * 8;
            float mx = -1e30f;
            #pragma unroll
            for (int n = 0; n < 8; n++) {
                #pragma unroll
                for (int e = 0; e < 2; e++) {
                    float s = sacc[n][half * 2 + e];
                    float v = SOFTCAP * fast_tanh(s * (ATTN_SCALE / SOFTCAP));
                    if (needmask) {
                        int kg = k0 + n * 8 + ((lane & 3) << 1) + e;
                        if (kg > qg) v = -1e30f;
                    }
                    sacc[n][half * 2 + e] = v;
                    mx = fmaxf(mx, v);
                }
            }
            mx = fmaxf(mx, __shfl_xor_sync(0xffffffffu, mx, 1));
            mx = fmaxf(mx, __shfl_xor_sync(0xffffffffu, mx, 2));
            float mnew = fmaxf(m_r[half], mx);
            float alpha = __expf(m_r[half] - mnew);
            m_r[half] = mnew;
            float ls = 0.f;
            #pragma unroll
            for (int n = 0; n < 8; n++) {
                #pragma unroll
                for (int e = 0; e < 2; e++) {
                    float p = __expf(sacc[n][half * 2 + e] - mnew);
                    sacc[n][half * 2 + e] = p;
                    ls += p;
                }
            }
            ls += __shfl_xor_sync(0xffffffffu, ls, 1);
            ls += __shfl_xor_sync(0xffffffffu, ls, 2);
            l_r[half] = l_r[half] * alpha + ls;
            #pragma unroll
            for (int dt = 0; dt < 16; dt++) {
                oacc[dt][half * 2 + 0] *= alpha;
                oacc[dt][half * 2 + 1] *= alpha;
            }
        }

        // ---- O += P V ----
        #pragma unroll
        for (int t = 0; t < 4; t++) {
            uint32_t pha[4], pla[4];
            pha[0] = pack_split(sacc[2*t][0],   sacc[2*t][1],   &pla[0]);
            pha[1] = pack_split(sacc[2*t][2],   sacc[2*t][3],   &pla[1]);
            pha[2] = pack_split(sacc[2*t+1][0], sacc[2*t+1][1], &pla[2]);
            pha[3] = pack_split(sacc[2*t+1][2], sacc[2*t+1][3], &pla[3]);
            #pragma unroll
            for (int dt = 0; dt < 8; dt++) {
                uint32_t vh4[4], vl4[4];
                uint32_t va = st + 2 * KVT_B
                            + (uint32_t)(t * 16 + lrow) * (QSTR * 2) + dt * 32 + lcol;
                LDSM_X4_T(vh4[0], vh4[1], vh4[2], vh4[3], va);
                LDSM_X4_T(vl4[0], vl4[1], vl4[2], vl4[3], va + KVT_B);
                mma16816(oacc[2*dt],     pha, vh4[0], vh4[1]);
                mma16816(oacc[2*dt],     pha, vl4[0], vl4[1]);
                mma16816(oacc[2*dt],     pla, vh4[0], vh4[1]);
                mma16816(oacc[2*dt+1],   pha, vh4[2], vh4[3]);
                mma16816(oacc[2*dt+1],   pha, vl4[2], vl4[3]);
                mma16816(oacc[2*dt+1],   pla, vh4[2], vh4[3]);
            }
        }
        __syncthreads();
    }

    // ---- epilogue: write split bf16 attention output directly ----
    float inv0 = 1.0f / l_r[0];
    float inv1 = 1.0f / l_r[1];
    #pragma unroll
    for (int dt = 0; dt < 16; dt++) {
        size_t r0 = hb + (size_t)qg0 * DMODEL + dt * 8 + (lane & 3) * 2;
        uint32_t lo0, lo1;
        uint32_t hi0 = pack_split(oacc[dt][0] * inv0, oacc[dt][1] * inv0, &lo0);
        uint32_t hi1 = pack_split(oacc[dt][2] * inv1, oacc[dt][3] * inv1, &lo1);
        *(uint32_t*)(Oh + r0) = hi0;
        *(uint32_t*)(Ol + r0) = lo0;
        *(uint32_t*)(Oh + r0 + 8 * DMODEL) = hi1;
        *(uint32_t*)(Ol + r0 + 8 * DMODEL) = lo1;
    }
}

// ----------------------------- launch -------------------------------------
extern "C" void kernel_launch(void* const* d_in, const int* in_sizes, int n_in,
                              void* d_out, int out_size) {
    const float* x        = (const float*)d_in[0];
    const float* wq       = (const float*)d_in[1];
    const float* wk       = (const float*)d_in[2];
    const float* wv       = (const float*)d_in[3];
    const float* wo       = (const float*)d_in[4];
    const float* q_norm_w = (const float*)d_in[5];
    const float* k_norm_w = (const float*)d_in[6];
    const float* rope_cos = (const float*)d_in[7];
    const float* rope_sin = (const float*)d_in[8];
    float* out = (float*)d_out;

    __nv_bfloat16 *xh, *xl, *ah, *al, *qh, *ql, *kh, *kl, *vh, *vl;
    __nv_bfloat16 *wqh, *wql, *wkh, *wkl, *wvh, *wvl, *woh, *wol;
    cudaGetSymbolAddress((void**)&xh, g_xh);   cudaGetSymbolAddress((void**)&xl, g_xl);
    cudaGetSymbolAddress((void**)&ah, g_ah);   cudaGetSymbolAddress((void**)&al, g_al);
    cudaGetSymbolAddress((void**)&qh, g_qh);   cudaGetSymbolAddress((void**)&ql, g_ql);
    cudaGetSymbolAddress((void**)&kh, g_kh);   cudaGetSymbolAddress((void**)&kl, g_kl);
    cudaGetSymbolAddress((void**)&vh, g_vh);   cudaGetSymbolAddress((void**)&vl, g_vl);
    cudaGetSymbolAddress((void**)&wqh, g_wqh); cudaGetSymbolAddress((void**)&wql, g_wql);
    cudaGetSymbolAddress((void**)&wkh, g_wkh); cudaGetSymbolAddress((void**)&wkl, g_wkl);
    cudaGetSymbolAddress((void**)&wvh, g_wvh); cudaGetSymbolAddress((void**)&wvl, g_wvl);
    cudaGetSymbolAddress((void**)&woh, g_woh); cudaGetSymbolAddress((void**)&wol, g_wol);

    cudaFuncSetAttribute(gemm_qkv, cudaFuncAttributeMaxDynamicSharedMemorySize,
                         GEMM_SMEM);
    cudaFuncSetAttribute(gemm_out, cudaFuncAttributeMaxDynamicSharedMemorySize,
                         GEMM_SMEM);
    cudaFuncSetAttribute(flash_mma, cudaFuncAttributeMaxDynamicSharedMemorySize,
                         FSMEM);

    // split conversions (weights separate so ncu -s 5 captures gemm_qkv)
    const int NX4 = ROWS * DMODEL / 4;
    const int NW4 = DMODEL * DMODEL / 4;
    split_bf16<<<NX4 / 256, 256>>>(x,  xh,  xl,  NX4);
    split_bf16<<<NW4 / 256, 256>>>(wq, wqh, wql, NW4);
    split_bf16<<<NW4 / 256, 256>>>(wk, wkh, wkl, NW4);
    split_bf16<<<NW4 / 256, 256>>>(wv, wvh, wvl, NW4);
    split_bf16<<<NW4 / 256, 256>>>(wo, woh, wol, NW4);

    // fused QKV projection + rmsnorm + rope + split epilogue
    dim3 qkvgrid(3 * NHEADS, ROWS / BM);    // 48 x 32
    gemm_qkv<<<qkvgrid, 256, GEMM_SMEM>>>(xh, xl,
        wqh, wql, wkh, wkl, wvh, wvl,
        qh, ql, kh, kl, vh, vl,
        q_norm_w, k_norm_w, rope_cos, rope_sin);

    // tensor-core flash attention (emits split bf16 output)
    dim3 fgrid(SEQ / FQ, NHEADS, BATCH);    // 16 x 16 x 2
    flash_mma<<<fgrid, 256, FSMEM>>>(qh, ql, kh, kl, vh, vl, ah, al);

    // output projection
    dim3 ogrid(DMODEL / BN, ROWS / BM);     // 16 x 32
    gemm_out<<<ogrid, 256, GEMM_SMEM>>>(ah, al, woh, wol, out);
}